// round 2
// baseline (speedup 1.0000x reference)
#include <cuda_runtime.h>
#include <math.h>

#define NN 100000
#define NE 1600000
#define NG 256
#define FIN 12
#define HID 64
#define FCD 140
#define SPLIT 8

// Scratch (static __device__ — no allocation allowed)
__device__ __align__(16) float g_g1[NN * HID];
__device__ __align__(16) float g_agg1[NN * HID];
__device__ __align__(16) float g_g2[NN * HID];
__device__ __align__(16) float g_agg2[NN * HID];
__device__ float g_dinv[NN];
__device__ int   g_deg[NN];
__device__ float g_pooled[NG * FCD];

// ---------------------------------------------------------------------------
// K0: per-launch re-init (graph replay safe): deg=1 (self-loop), pooled=0
__global__ void k_init() {
    int i = blockIdx.x * blockDim.x + threadIdx.x;
    if (i < NN) g_deg[i] = 1;
    if (i < NG * FCD) g_pooled[i] = 0.0f;
}

// K1: in-degree over dst (edge_index row 1)
__global__ void k_deg(const int* __restrict__ ei) {
    int e = blockIdx.x * blockDim.x + threadIdx.x;
    if (e < NE) atomicAdd(&g_deg[ei[NE + e]], 1);
}

// K2: dinv = rsqrt(deg)
__global__ void k_dinv() {
    int i = blockIdx.x * blockDim.x + threadIdx.x;
    if (i < NN) g_dinv[i] = rsqrtf((float)g_deg[i]);
}

// K3: g1 = dinv * (x @ W1);  agg1 = g1 (self-loop term pre-seeded)
__global__ void k_xw1(const float* __restrict__ x, const float* __restrict__ W1) {
    __shared__ float sW[FIN * HID];
    for (int i = threadIdx.x; i < FIN * HID; i += blockDim.x) sW[i] = W1[i];
    __syncthreads();
    int gid = blockIdx.x * blockDim.x + threadIdx.x;
    if (gid >= NN * HID) return;
    int node = gid >> 6;
    int f    = gid & 63;
    const float* xr = x + node * FIN;
    float s = 0.0f;
#pragma unroll
    for (int k = 0; k < FIN; k++) s += xr[k] * sW[k * HID + f];
    float v = g_dinv[node] * s;
    g_g1[gid]   = v;
    g_agg1[gid] = v;
}

// K4/K6: edge scatter. 16 threads per edge, float4 per thread, vector red.
__global__ void k_edge(const int* __restrict__ ei, int layer) {
    int gid = blockIdx.x * blockDim.x + threadIdx.x;
    int e = gid >> 4;
    if (e >= NE) return;
    int c   = gid & 15;
    int src = ei[e];
    int dst = ei[NE + e];
    const float4* g   = layer ? (const float4*)g_g2  : (const float4*)g_g1;
    float4*       agg = layer ? (float4*)g_agg2 : (float4*)g_agg1;
    float4 v = g[src * 16 + c];
    float4* p = agg + dst * 16 + c;
    asm volatile("red.global.add.v4.f32 [%0], {%1,%2,%3,%4};"
                 :: "l"(p), "f"(v.x), "f"(v.y), "f"(v.z), "f"(v.w)
                 : "memory");
}

// K5: h1 = tanh(dinv*agg1 + b1) (recomputed, kept in smem only);
//     g2 = dinv * (h1 @ W2); agg2 = g2.  32 nodes per 256-thread block.
__global__ void k_l2(const float* __restrict__ W2, const float* __restrict__ b1) {
    __shared__ float sW[HID * HID];   // 16 KB
    __shared__ float sh[32 * HID];    // 8 KB
    int tid = threadIdx.x;
    for (int i = tid; i < HID * HID; i += 256) sW[i] = W2[i];
    int n0 = blockIdx.x * 32;
    for (int i = tid; i < 32 * HID; i += 256) {
        int node = n0 + (i >> 6);
        int f    = i & 63;
        sh[i] = tanhf(g_dinv[node] * g_agg1[node * HID + f] + b1[f]);
    }
    __syncthreads();
    for (int i = tid; i < 32 * HID; i += 256) {
        int ln = i >> 6;
        int f  = i & 63;
        const float* hr = sh + ln * HID;
        float s = 0.0f;
#pragma unroll 8
        for (int k = 0; k < HID; k++) s += hr[k] * sW[k * HID + f];
        int node = n0 + ln;
        float v = g_dinv[node] * s;
        g_g2[node * HID + f]   = v;
        g_agg2[node * HID + f] = v;
    }
}

// K7: pooling. batch is sorted -> block per (graph, split). Each of 140 lanes
// owns one feature; h1/h2 recomputed from agg buffers on the fly.
__global__ void k_pool(const float* __restrict__ x,
                       const float* __restrict__ b1,
                       const float* __restrict__ b2,
                       const int* __restrict__ batch) {
    int g = blockIdx.x / SPLIT;
    int s = blockIdx.x % SPLIT;
    int f = threadIdx.x;

    // lower_bound(g), lower_bound(g+1) over sorted batch
    int a = 0, b = NN;
    while (a < b) { int m = (a + b) >> 1; if (batch[m] < g) a = m + 1; else b = m; }
    int lo = a;
    a = lo; b = NN;
    while (a < b) { int m = (a + b) >> 1; if (batch[m] < g + 1) a = m + 1; else b = m; }
    int hi = a;

    int cnt = hi - lo;
    int per = (cnt + SPLIT - 1) / SPLIT;
    int st  = lo + s * per;
    int en  = min(st + per, hi);

    if (f < FCD) {
        float acc = 0.0f;
        for (int node = st; node < en; node++) {
            float v;
            if (f < FIN) {
                v = x[node * FIN + f];
            } else if (f < FIN + HID) {
                int k = f - FIN;
                v = tanhf(g_dinv[node] * g_agg1[node * HID + k] + b1[k]);
            } else {
                int k = f - FIN - HID;
                v = tanhf(g_dinv[node] * g_agg2[node * HID + k] + b2[k]);
            }
            acc += v;
        }
        if (st < en) atomicAdd(&g_pooled[g * FCD + f], acc);
    }
}

// K8: out[g,o] = sum_k pooled[g,k] * fc_W[o,k] + fc_b[o]
__global__ void k_fc(const float* __restrict__ fcW,
                     const float* __restrict__ fcb,
                     float* __restrict__ out) {
    __shared__ float sp[FCD];
    int g = blockIdx.x;
    for (int i = threadIdx.x; i < FCD; i += blockDim.x) sp[i] = g_pooled[g * FCD + i];
    __syncthreads();
    int o = threadIdx.x;
    if (o < FCD) {
        const float* wr = fcW + o * FCD;
        float s = fcb[o];
        for (int k = 0; k < FCD; k++) s += sp[k] * wr[k];
        out[g * FCD + o] = s;
    }
}

// ---------------------------------------------------------------------------
extern "C" void kernel_launch(void* const* d_in, const int* in_sizes, int n_in,
                              void* d_out, int out_size) {
    const float* x    = (const float*)d_in[0];
    const float* W1   = (const float*)d_in[1];
    const float* b1   = (const float*)d_in[2];
    const float* W2   = (const float*)d_in[3];
    const float* b2   = (const float*)d_in[4];
    const float* fcW  = (const float*)d_in[5];
    const float* fcb  = (const float*)d_in[6];
    const int*   ei   = (const int*)d_in[7];     // int32 (JAX x64 disabled)
    const int*   batch= (const int*)d_in[8];     // int32
    // d_in[9] = edge_index_cg: unused by the reference computation
    float* out = (float*)d_out;
    (void)in_sizes; (void)n_in; (void)out_size;

    k_init<<<(NN + 255) / 256, 256>>>();
    k_deg <<<(NE + 255) / 256, 256>>>(ei);
    k_dinv<<<(NN + 255) / 256, 256>>>();
    k_xw1 <<<(NN * HID) / 256, 256>>>(x, W1);
    k_edge<<<(NE * 16) / 256, 256>>>(ei, 0);
    k_l2  <<<NN / 32, 256>>>(W2, b1);
    k_edge<<<(NE * 16) / 256, 256>>>(ei, 1);
    k_pool<<<NG * SPLIT, 160>>>(x, b1, b2, batch);
    k_fc  <<<NG, 160>>>(fcW, fcb, out);
}